// round 16
// baseline (speedup 1.0000x reference)
#include <cuda_runtime.h>
#include <cstdint>

#define BB   8
#define SS   4096
#define HIDD 1024
#define HH   16
#define DHH  64

#define MT    128                // rows per tile
#define KC    32                 // k-chunk (floats)
#define NC    (HIDD / KC)        // 32
#define TILES 32
#define NBLK  (BB * TILES)       // 256

#define CR    8                  // k1b rows per staging chunk
#define NCH   (MT / CR)          // 16 chunks

// ---------- static scratch ----------
__device__ float g_scratch[(size_t)NBLK * HH * HIDD]; // 16.8 MB
__device__ float hbar_scratch[(size_t)NBLK * HIDD];   // 1 MB
__device__ float wqk_eff[2 * HH * HIDD];
__device__ float qs_buf[(size_t)BB * SS * HH];        // 2 MB
__device__ float ks_buf[(size_t)BB * SS * HH];        // 2 MB
__device__ float gsum_buf[BB * HH * HIDD];            // 512 KB
__device__ float hsum_buf[BB * HIDD];                 // 32 KB
__device__ float kv_buf[BB * HH * DHH];
__device__ float mv_buf[BB * HH * DHH];
__device__ float invlen_buf[BB];

typedef unsigned long long u64;

__device__ __forceinline__ u64 ffma2(u64 a, u64 b, u64 c) {
    u64 d;
    asm("fma.rn.f32x2 %0, %1, %2, %3;" : "=l"(d) : "l"(a), "l"(b), "l"(c));
    return d;
}
__device__ __forceinline__ u64 pack2(float x, float y) {
    u64 r; asm("mov.b64 %0, {%1,%2};" : "=l"(r) : "f"(x), "f"(y)); return r;
}
__device__ __forceinline__ float2 unpack2(u64 v) {
    float2 r; asm("mov.b64 {%0,%1}, %2;" : "=f"(r.x), "=f"(r.y) : "l"(v)); return r;
}
__device__ __forceinline__ uint32_t smem_u32(const void* p) {
    uint32_t a;
    asm("{ .reg .u64 t; cvta.to.shared.u64 t, %1; cvt.u32.u64 %0, t; }" : "=r"(a) : "l"(p));
    return a;
}
__device__ __forceinline__ void cp16(uint32_t dst, const void* src) {
    asm volatile("cp.async.cg.shared.global [%0], [%1], 16;" :: "r"(dst), "l"(src) : "memory");
}
__device__ __forceinline__ void cp16ca(uint32_t dst, const void* src) {
    asm volatile("cp.async.ca.shared.global [%0], [%1], 16;" :: "r"(dst), "l"(src) : "memory");
}
__device__ __forceinline__ void cp_commit() {
    asm volatile("cp.async.commit_group;" ::: "memory");
}
__device__ __forceinline__ void cp_wait0() {
    asm volatile("cp.async.wait_group 0;" ::: "memory");
}

// ============================================================
// K0: blocks 0..31 weff ; blocks 32..39 invlen
// ============================================================
__global__ void k0_weff(const float* __restrict__ Wq,
                        const float* __restrict__ Wk,
                        const float* __restrict__ aw,
                        const float* __restrict__ mask) {
    if (blockIdx.x >= 32) {
        int b = blockIdx.x - 32;
        __shared__ float red[256];
        float s = 0.f;
        for (int i = threadIdx.x; i < SS; i += 256) s += mask[(size_t)b * SS + i];
        red[threadIdx.x] = s;
        __syncthreads();
        for (int st = 128; st > 0; st >>= 1) {
            if (threadIdx.x < st) red[threadIdx.x] += red[threadIdx.x + st];
            __syncthreads();
        }
        if (threadIdx.x == 0) invlen_buf[b] = 1.f / red[0];
        return;
    }
    int ch = blockIdx.x >> 4, h = blockIdx.x & 15;
    const float* W = ch ? Wk : Wq;
    __shared__ float a_sh[DHH];
    if (threadIdx.x < DHH) a_sh[threadIdx.x] = aw[h * DHH + threadIdx.x];
    __syncthreads();
    for (int e = threadIdx.x; e < HIDD; e += blockDim.x) {
        float acc = 0.f;
#pragma unroll 8
        for (int d = 0; d < DHH; d++)
            acc += a_sh[d] * W[(size_t)(h * DHH + d) * HIDD + e];
        wqk_eff[(ch * HH + h) * HIDD + e] = acc;
    }
}

// ============================================================
// K1a: GEMM C[128x32] = tile x wqk_eff^T. 128 threads, tile 8x4,
// k-paired FFMA2, 2-stage cp.async (R9 — proven optimum).
// ============================================================
__global__ void __launch_bounds__(128, 3)
k1a_gemm(const float* __restrict__ hidden, const float* __restrict__ mask) {
    __shared__ float As[2][MT][36];
    __shared__ float Bt[2][32][36];

    const int tile = blockIdx.x;
    const int b = tile >> 5;
    const int s0 = (tile & 31) * MT;
    const int tid = threadIdx.x;
    const int tx = tid & 7;
    const int ty = tid >> 3;

    const float* Ab = hidden + ((size_t)b * SS + s0) * HIDD;

    uint32_t a_dst[2][8], b_dst[2][2];
    const float* a_src[8];
    const float* b_src[2];
#pragma unroll
    for (int i = 0; i < 8; i++) {
        int unit = tid + i * 128;
        int r = unit >> 3, kq = unit & 7;
        a_dst[0][i] = smem_u32(&As[0][r][kq * 4]);
        a_dst[1][i] = smem_u32(&As[1][r][kq * 4]);
        a_src[i] = Ab + (size_t)r * HIDD + kq * 4;
    }
#pragma unroll
    for (int p = 0; p < 2; p++) {
        int unit = tid + p * 128;
        int v = unit >> 3, kq = unit & 7;
        b_dst[0][p] = smem_u32(&Bt[0][v][kq * 4]);
        b_dst[1][p] = smem_u32(&Bt[1][v][kq * 4]);
        b_src[p] = wqk_eff + (size_t)v * HIDD + kq * 4;
    }

    u64 acc[8][4];
#pragma unroll
    for (int i = 0; i < 8; i++)
#pragma unroll
        for (int j = 0; j < 4; j++) acc[i][j] = 0ull;

#pragma unroll
    for (int i = 0; i < 8; i++) cp16ca(a_dst[0][i], a_src[i]);
#pragma unroll
    for (int p = 0; p < 2; p++) cp16ca(b_dst[0][p], b_src[p]);
    cp_commit();
    cp_wait0();
    __syncthreads();

#pragma unroll 1
    for (int c = 0; c < NC; c++) {
        const int cur = c & 1, nxt = cur ^ 1;
        if (c + 1 < NC) {
            int k0 = (c + 1) * KC;
#pragma unroll
            for (int i = 0; i < 8; i++) cp16ca(a_dst[nxt][i], a_src[i] + k0);
#pragma unroll
            for (int p = 0; p < 2; p++) cp16ca(b_dst[nxt][p], b_src[p] + k0);
            cp_commit();
        }
#pragma unroll
        for (int k = 0; k < KC; k += 2) {
            u64 a[8], bv[4];
#pragma unroll
            for (int i = 0; i < 8; i++) a[i] = *(const u64*)&As[cur][ty + 16 * i][k];
#pragma unroll
            for (int j = 0; j < 4; j++) bv[j] = *(const u64*)&Bt[cur][tx + 8 * j][k];
#pragma unroll
            for (int i = 0; i < 8; i++) {
                acc[i][0] = ffma2(a[i], bv[0], acc[i][0]);
                acc[i][1] = ffma2(a[i], bv[1], acc[i][1]);
                acc[i][2] = ffma2(a[i], bv[2], acc[i][2]);
                acc[i][3] = ffma2(a[i], bv[3], acc[i][3]);
            }
        }
        if (c + 1 < NC) cp_wait0();
        __syncthreads();
    }

#pragma unroll
    for (int i = 0; i < 8; i++) {
        int row = ty + 16 * i;
        float m = mask[(size_t)b * SS + s0 + row];
        float2 f0 = unpack2(acc[i][0]);
        float2 f1 = unpack2(acc[i][1]);
        float2 f2 = unpack2(acc[i][2]);
        float2 f3 = unpack2(acc[i][3]);
        size_t rb = ((size_t)(b * SS + s0 + row)) * HH;
        qs_buf[rb + tx]     = (f0.x + f0.y) * m;
        qs_buf[rb + tx + 8] = (f1.x + f1.y) * m;
        ks_buf[rb + tx]     = (f2.x + f2.y) * m;
        ks_buf[rb + tx + 8] = (f3.x + f3.y) * m;
    }
}

// ---------- dynamic smem layout for k1b ----------
// Rs:     [2][CR][1024] float = 65536 B
// ks_dup: [MT][16] u64        = 16384 B  @ 65536
// m_dup:  [MT] u64            =  1024 B  @ 81920
#define K1B_RS   0
#define K1B_KS   65536
#define K1B_MD   (K1B_KS + 16384)
#define K1B_TOT  (K1B_MD + 1024)      // 82944 B -> occ 2 (166 KB <= 228)

// ============================================================
// K1b: g[h][e] += ks[s][h]*H[s][e] ; hbar[e] += m[s]*H[s][e]
// Hidden rows staged via double-buffered cp.async (CR=8 rows / 32KB
// chunks, R9 schedule) -> DRAM latency fully hidden; compute reads
// coalesced conflict-free LDS.128. Same math as R9.
// ============================================================
__global__ void __launch_bounds__(256, 2)
k1b_accum(const float* __restrict__ hidden, const float* __restrict__ mask) {
    extern __shared__ char smem_raw[];
    float (*Rs)[CR][1024] = reinterpret_cast<float (*)[CR][1024]>(smem_raw + K1B_RS);
    u64   (*ks_dup)[16]   = reinterpret_cast<u64 (*)[16]>(smem_raw + K1B_KS);
    u64*  m_dup           = reinterpret_cast<u64*>(smem_raw + K1B_MD);

    const int tile = blockIdx.x;
    const int b = tile >> 5;
    const int s0 = (tile & 31) * MT;
    const int tid = threadIdx.x;
    const float* Ab = hidden + ((size_t)b * SS + s0) * HIDD;

    // staging decode: 2048 16B-units per chunk, 8 per thread
    uint32_t r_dst[2][8];
    const float* r_src[8];
#pragma unroll
    for (int i = 0; i < 8; i++) {
        int unit = tid + i * 256;        // 0..2047
        int rr = unit >> 8;              // row in chunk (0..7)
        int off = unit & 255;            // 16B unit within row
        r_dst[0][i] = smem_u32(&Rs[0][rr][off * 4]);
        r_dst[1][i] = smem_u32(&Rs[1][rr][off * 4]);
        r_src[i] = Ab + (size_t)rr * HIDD + off * 4;
    }

    // prologue: stage chunk 0 (overlaps with ks/m loads below)
#pragma unroll
    for (int i = 0; i < 8; i++) cp16(r_dst[0][i], r_src[i]);
    cp_commit();

    // ks_dup + m_dup
#pragma unroll
    for (int p = 0; p < 8; p++) {
        int idx = tid + 256 * p;
        int r = idx >> 4, h = idx & 15;
        float v = ks_buf[((size_t)(b * SS + s0 + r)) * HH + h];
        ks_dup[r][h] = pack2(v, v);
    }
    if (tid < MT) {
        float m = mask[(size_t)b * SS + s0 + tid];
        m_dup[tid] = pack2(m, m);
    }
    cp_wait0();
    __syncthreads();

    u64 g[16][2];
#pragma unroll
    for (int h = 0; h < 16; h++) { g[h][0] = 0ull; g[h][1] = 0ull; }
    u64 hb0 = 0ull, hb1 = 0ull;

#pragma unroll 1
    for (int c = 0; c < NCH; c++) {
        const int cur = c & 1, nxt = cur ^ 1;
        if (c + 1 < NCH) {
            size_t roff = (size_t)(c + 1) * CR * HIDD;
#pragma unroll
            for (int i = 0; i < 8; i++) cp16(r_dst[nxt][i], r_src[i] + roff);
            cp_commit();
        }
#pragma unroll
        for (int r = 0; r < CR; r++) {
            int row = c * CR + r;
            float4 hf = *(const float4*)&Rs[cur][r][tid * 4];
            ulonglong2 hv;
            hv.x = pack2(hf.x, hf.y);
            hv.y = pack2(hf.z, hf.w);
            u64 md = m_dup[row];
            hb0 = ffma2(hv.x, md, hb0);
            hb1 = ffma2(hv.y, md, hb1);
#pragma unroll
            for (int hh = 0; hh < 8; hh++) {
                ulonglong2 kp = *(const ulonglong2*)&ks_dup[row][hh * 2];
                g[2 * hh + 0][0] = ffma2(hv.x, kp.x, g[2 * hh + 0][0]);
                g[2 * hh + 0][1] = ffma2(hv.y, kp.x, g[2 * hh + 0][1]);
                g[2 * hh + 1][0] = ffma2(hv.x, kp.y, g[2 * hh + 1][0]);
                g[2 * hh + 1][1] = ffma2(hv.y, kp.y, g[2 * hh + 1][1]);
            }
        }
        if (c + 1 < NCH) cp_wait0();
        __syncthreads();
    }

#pragma unroll
    for (int h = 0; h < 16; h++) {
        float2 x = unpack2(g[h][0]), y = unpack2(g[h][1]);
        *(float4*)(g_scratch + ((size_t)tile * HH + h) * HIDD + tid * 4) =
            make_float4(x.x, x.y, y.x, y.y);
    }
    {
        float2 x = unpack2(hb0), y = unpack2(hb1);
        *(float4*)(hbar_scratch + (size_t)tile * HIDD + tid * 4) =
            make_float4(x.x, x.y, y.x, y.y);
    }
}

// ============================================================
// K2r: parallel reduction g_scratch -> gsum_buf, hbar -> hsum_buf (R9)
// ============================================================
__global__ void __launch_bounds__(256)
k2r_reduce() {
    int bid = blockIdx.x;
    if (bid < 512) {
        int b = bid >> 6, h = (bid >> 2) & 15, seg = bid & 3;
        int e = seg * 256 + threadIdx.x;
        const float* base = g_scratch + (((size_t)b * TILES) * HH + h) * HIDD + e;
        float a[4];
#pragma unroll
        for (int j = 0; j < 4; j++) a[j] = 0.f;
#pragma unroll
        for (int c = 0; c < TILES; c += 4) {
            float t[4];
#pragma unroll
            for (int j = 0; j < 4; j++) t[j] = base[(size_t)(c + j) * HH * HIDD];
#pragma unroll
            for (int j = 0; j < 4; j++) a[j] += t[j];
        }
        gsum_buf[((b * HH + h) << 10) + e] = (a[0] + a[1]) + (a[2] + a[3]);
    } else {
        int bid2 = bid - 512;
        int b = bid2 >> 2, seg = bid2 & 3;
        int e = seg * 256 + threadIdx.x;
        const float* base = hbar_scratch + ((size_t)b * TILES) * HIDD + e;
        float a[4];
#pragma unroll
        for (int j = 0; j < 4; j++) a[j] = 0.f;
#pragma unroll
        for (int c = 0; c < TILES; c += 4) {
            float t[4];
#pragma unroll
            for (int j = 0; j < 4; j++) t[j] = base[(size_t)(c + j) * HIDD];
#pragma unroll
            for (int j = 0; j < 4; j++) a[j] += t[j];
        }
        hsum_buf[(b << 10) + e] = (a[0] + a[1]) + (a[2] + a[3]);
    }
}

// ============================================================
// K2d: per (b,h): kv/mv = (gsum|hsum) . Wv rows (R9)
// ============================================================
__global__ void __launch_bounds__(256)
k2d_dot(const float* __restrict__ Wv) {
    int b = blockIdx.x >> 4, h = blockIdx.x & 15;
    __shared__ float gsum[HIDD];
    __shared__ float hsum[HIDD];

    {
        int t4 = threadIdx.x * 4;
        *(float4*)&gsum[t4] = *(const float4*)(gsum_buf + ((b * HH + h) << 10) + t4);
        *(float4*)&hsum[t4] = *(const float4*)(hsum_buf + (b << 10) + t4);
    }
    __syncthreads();

    int w = threadIdx.x >> 5, l = threadIdx.x & 31;
#pragma unroll
    for (int dd = 0; dd < 8; dd++) {
        int d = w * 8 + dd;
        const float* wvrow = Wv + (size_t)(h * DHH + d) * HIDD;
        float ak = 0.f, am = 0.f;
#pragma unroll 8
        for (int e2 = l; e2 < HIDD; e2 += 32) {
            float wv = __ldg(wvrow + e2);
            ak += gsum[e2] * wv;
            am += hsum[e2] * wv;
        }
#pragma unroll
        for (int off = 16; off > 0; off >>= 1) {
            ak += __shfl_xor_sync(0xffffffffu, ak, off);
            am += __shfl_xor_sync(0xffffffffu, am, off);
        }
        if (l == 0) {
            kv_buf[((b * HH + h) << 6) + d] = ak;
            mv_buf[((b * HH + h) << 6) + d] = am;
        }
    }
}

// ============================================================
// K3: out = (qs*mv + kv)*invlen (R9)
// ============================================================
__global__ void k3_out(float* __restrict__ out) {
    int row0 = blockIdx.x << 3;
    int b = row0 >> 12;
    int t = threadIdx.x;
    int h = t >> 4;
    int d = (t & 15) << 2;
    float4 mv4 = *(const float4*)(mv_buf + ((b * HH + h) << 6) + d);
    float4 kv4 = *(const float4*)(kv_buf + ((b * HH + h) << 6) + d);
    float il = invlen_buf[b];
    float4 mvi = make_float4(mv4.x * il, mv4.y * il, mv4.z * il, mv4.w * il);
    float4 kvi = make_float4(kv4.x * il, kv4.y * il, kv4.z * il, kv4.w * il);
#pragma unroll
    for (int rr = 0; rr < 8; rr++) {
        int row = row0 + rr;
        float qsv = __ldg(qs_buf + (size_t)row * HH + h);
        float4 o;
        o.x = qsv * mvi.x + kvi.x;
        o.y = qsv * mvi.y + kvi.y;
        o.z = qsv * mvi.z + kvi.z;
        o.w = qsv * mvi.w + kvi.w;
        __stcs(((float4*)out) + (size_t)row * 256 + t, o);
    }
}

// ============================================================
extern "C" void kernel_launch(void* const* d_in, const int* in_sizes, int n_in,
                              void* d_out, int out_size) {
    const float* hidden = (const float*)d_in[0];
    const float* mask   = (const float*)d_in[1];
    const float* Wq     = (const float*)d_in[2];
    const float* Wk     = (const float*)d_in[3];
    const float* Wv     = (const float*)d_in[4];
    const float* aw     = (const float*)d_in[5];
    float* out = (float*)d_out;

    cudaFuncSetAttribute(k1b_accum, cudaFuncAttributeMaxDynamicSharedMemorySize, K1B_TOT);

    k0_weff<<<40, 256>>>(Wq, Wk, aw, mask);
    k1a_gemm<<<NBLK, 128>>>(hidden, mask);
    k1b_accum<<<NBLK, 256, K1B_TOT>>>(hidden, mask);
    k2r_reduce<<<544, 256>>>();
    k2d_dot<<<BB * HH, 256>>>(Wv);
    k3_out<<<BB * SS / 8, 256>>>(out);
}

// round 17
// speedup vs baseline: 1.0772x; 1.0772x over previous
#include <cuda_runtime.h>
#include <cstdint>

#define BB   8
#define SS   4096
#define HIDD 1024
#define HH   16
#define DHH  64

#define MT    128                // rows per tile
#define KC    32                 // k-chunk (floats)
#define NC    (HIDD / KC)        // 32
#define TILES 32
#define NBLK  (BB * TILES)       // 256

// ---------- static scratch ----------
__device__ float g_scratch[(size_t)NBLK * HH * HIDD]; // 16.8 MB
__device__ float hbar_scratch[(size_t)NBLK * HIDD];   // 1 MB
__device__ float wqk_eff[2 * HH * HIDD];
__device__ float qs_buf[(size_t)BB * SS * HH];        // 2 MB
__device__ float ks_buf[(size_t)BB * SS * HH];        // 2 MB
__device__ float kv_buf[BB * HH * DHH];
__device__ float mv_buf[BB * HH * DHH];
__device__ float invlen_buf[BB];

typedef unsigned long long u64;

__device__ __forceinline__ u64 ffma2(u64 a, u64 b, u64 c) {
    u64 d;
    asm("fma.rn.f32x2 %0, %1, %2, %3;" : "=l"(d) : "l"(a), "l"(b), "l"(c));
    return d;
}
__device__ __forceinline__ u64 pack2(float x, float y) {
    u64 r; asm("mov.b64 %0, {%1,%2};" : "=l"(r) : "f"(x), "f"(y)); return r;
}
__device__ __forceinline__ float2 unpack2(u64 v) {
    float2 r; asm("mov.b64 {%0,%1}, %2;" : "=f"(r.x), "=f"(r.y) : "l"(v)); return r;
}
__device__ __forceinline__ uint32_t smem_u32(const void* p) {
    uint32_t a;
    asm("{ .reg .u64 t; cvta.to.shared.u64 t, %1; cvt.u32.u64 %0, t; }" : "=r"(a) : "l"(p));
    return a;
}
__device__ __forceinline__ void cp16(uint32_t dst, const void* src) {
    asm volatile("cp.async.ca.shared.global [%0], [%1], 16;" :: "r"(dst), "l"(src) : "memory");
}
__device__ __forceinline__ void cp_commit() {
    asm volatile("cp.async.commit_group;" ::: "memory");
}
__device__ __forceinline__ void cp_wait0() {
    asm volatile("cp.async.wait_group 0;" ::: "memory");
}

// ============================================================
// K0: blocks 0..31 weff ; blocks 32..39 invlen
// ============================================================
__global__ void k0_weff(const float* __restrict__ Wq,
                        const float* __restrict__ Wk,
                        const float* __restrict__ aw,
                        const float* __restrict__ mask) {
    if (blockIdx.x >= 32) {
        int b = blockIdx.x - 32;
        __shared__ float red[256];
        float s = 0.f;
        for (int i = threadIdx.x; i < SS; i += 256) s += mask[(size_t)b * SS + i];
        red[threadIdx.x] = s;
        __syncthreads();
        for (int st = 128; st > 0; st >>= 1) {
            if (threadIdx.x < st) red[threadIdx.x] += red[threadIdx.x + st];
            __syncthreads();
        }
        if (threadIdx.x == 0) invlen_buf[b] = 1.f / red[0];
        return;
    }
    int ch = blockIdx.x >> 4, h = blockIdx.x & 15;
    const float* W = ch ? Wk : Wq;
    __shared__ float a_sh[DHH];
    if (threadIdx.x < DHH) a_sh[threadIdx.x] = aw[h * DHH + threadIdx.x];
    __syncthreads();
    for (int e = threadIdx.x; e < HIDD; e += blockDim.x) {
        float acc = 0.f;
#pragma unroll 8
        for (int d = 0; d < DHH; d++)
            acc += a_sh[d] * W[(size_t)(h * DHH + d) * HIDD + e];
        wqk_eff[(ch * HH + h) * HIDD + e] = acc;
    }
}

// ============================================================
// K1a: GEMM C[128x32] = tile x wqk_eff^T. 128 threads, tile 8x4,
// k-paired FFMA2, 2-stage cp.async (R9 — proven optimum).
// ============================================================
__global__ void __launch_bounds__(128, 3)
k1a_gemm(const float* __restrict__ hidden, const float* __restrict__ mask) {
    __shared__ float As[2][MT][36];
    __shared__ float Bt[2][32][36];

    const int tile = blockIdx.x;
    const int b = tile >> 5;
    const int s0 = (tile & 31) * MT;
    const int tid = threadIdx.x;
    const int tx = tid & 7;
    const int ty = tid >> 3;

    const float* Ab = hidden + ((size_t)b * SS + s0) * HIDD;

    uint32_t a_dst[2][8], b_dst[2][2];
    const float* a_src[8];
    const float* b_src[2];
#pragma unroll
    for (int i = 0; i < 8; i++) {
        int unit = tid + i * 128;
        int r = unit >> 3, kq = unit & 7;
        a_dst[0][i] = smem_u32(&As[0][r][kq * 4]);
        a_dst[1][i] = smem_u32(&As[1][r][kq * 4]);
        a_src[i] = Ab + (size_t)r * HIDD + kq * 4;
    }
#pragma unroll
    for (int p = 0; p < 2; p++) {
        int unit = tid + p * 128;
        int v = unit >> 3, kq = unit & 7;
        b_dst[0][p] = smem_u32(&Bt[0][v][kq * 4]);
        b_dst[1][p] = smem_u32(&Bt[1][v][kq * 4]);
        b_src[p] = wqk_eff + (size_t)v * HIDD + kq * 4;
    }

    u64 acc[8][4];
#pragma unroll
    for (int i = 0; i < 8; i++)
#pragma unroll
        for (int j = 0; j < 4; j++) acc[i][j] = 0ull;

#pragma unroll
    for (int i = 0; i < 8; i++) cp16(a_dst[0][i], a_src[i]);
#pragma unroll
    for (int p = 0; p < 2; p++) cp16(b_dst[0][p], b_src[p]);
    cp_commit();
    cp_wait0();
    __syncthreads();

#pragma unroll 1
    for (int c = 0; c < NC; c++) {
        const int cur = c & 1, nxt = cur ^ 1;
        if (c + 1 < NC) {
            int k0 = (c + 1) * KC;
#pragma unroll
            for (int i = 0; i < 8; i++) cp16(a_dst[nxt][i], a_src[i] + k0);
#pragma unroll
            for (int p = 0; p < 2; p++) cp16(b_dst[nxt][p], b_src[p] + k0);
            cp_commit();
        }
#pragma unroll
        for (int k = 0; k < KC; k += 2) {
            u64 a[8], bv[4];
#pragma unroll
            for (int i = 0; i < 8; i++) a[i] = *(const u64*)&As[cur][ty + 16 * i][k];
#pragma unroll
            for (int j = 0; j < 4; j++) bv[j] = *(const u64*)&Bt[cur][tx + 8 * j][k];
#pragma unroll
            for (int i = 0; i < 8; i++) {
                acc[i][0] = ffma2(a[i], bv[0], acc[i][0]);
                acc[i][1] = ffma2(a[i], bv[1], acc[i][1]);
                acc[i][2] = ffma2(a[i], bv[2], acc[i][2]);
                acc[i][3] = ffma2(a[i], bv[3], acc[i][3]);
            }
        }
        if (c + 1 < NC) cp_wait0();
        __syncthreads();
    }

#pragma unroll
    for (int i = 0; i < 8; i++) {
        int row = ty + 16 * i;
        float m = mask[(size_t)b * SS + s0 + row];
        float2 f0 = unpack2(acc[i][0]);
        float2 f1 = unpack2(acc[i][1]);
        float2 f2 = unpack2(acc[i][2]);
        float2 f3 = unpack2(acc[i][3]);
        size_t rb = ((size_t)(b * SS + s0 + row)) * HH;
        qs_buf[rb + tx]     = (f0.x + f0.y) * m;
        qs_buf[rb + tx + 8] = (f1.x + f1.y) * m;
        ks_buf[rb + tx]     = (f2.x + f2.y) * m;
        ks_buf[rb + tx + 8] = (f3.x + f3.y) * m;
    }
}

// ============================================================
// K1b: g[h][e] += ks[s][h]*H[s][e] ; hbar[e] += m[s]*H[s][e]  (R9)
// ============================================================
__global__ void __launch_bounds__(256, 2)
k1b_accum(const float* __restrict__ hidden, const float* __restrict__ mask) {
    __shared__ u64 ks_dup[MT][16];
    __shared__ u64 m_dup[MT];

    const int tile = blockIdx.x;
    const int b = tile >> 5;
    const int s0 = (tile & 31) * MT;
    const int tid = threadIdx.x;
    const float* Ab = hidden + ((size_t)b * SS + s0) * HIDD;

#pragma unroll
    for (int p = 0; p < 8; p++) {
        int idx = tid + 256 * p;
        int r = idx >> 4, h = idx & 15;
        float v = ks_buf[((size_t)(b * SS + s0 + r)) * HH + h];
        ks_dup[r][h] = pack2(v, v);
    }
    if (tid < MT) {
        float m = mask[(size_t)b * SS + s0 + tid];
        m_dup[tid] = pack2(m, m);
    }
    __syncthreads();

    u64 g[16][2];
#pragma unroll
    for (int h = 0; h < 16; h++) { g[h][0] = 0ull; g[h][1] = 0ull; }
    u64 hb0 = 0ull, hb1 = 0ull;

    const float4* hrow = (const float4*)(Ab + tid * 4);
#pragma unroll 1
    for (int r0 = 0; r0 < MT; r0 += 4) {
        float4 hf[4];
#pragma unroll
        for (int u = 0; u < 4; u++)
            hf[u] = __ldcs(hrow + (size_t)(r0 + u) * (HIDD / 4));
#pragma unroll
        for (int u = 0; u < 4; u++) {
            ulonglong2 hv;
            hv.x = pack2(hf[u].x, hf[u].y);
            hv.y = pack2(hf[u].z, hf[u].w);
            u64 md = m_dup[r0 + u];
            hb0 = ffma2(hv.x, md, hb0);
            hb1 = ffma2(hv.y, md, hb1);
#pragma unroll
            for (int hh = 0; hh < 8; hh++) {
                ulonglong2 kp = *(const ulonglong2*)&ks_dup[r0 + u][hh * 2];
                g[2 * hh + 0][0] = ffma2(hv.x, kp.x, g[2 * hh + 0][0]);
                g[2 * hh + 0][1] = ffma2(hv.y, kp.x, g[2 * hh + 0][1]);
                g[2 * hh + 1][0] = ffma2(hv.x, kp.y, g[2 * hh + 1][0]);
                g[2 * hh + 1][1] = ffma2(hv.y, kp.y, g[2 * hh + 1][1]);
            }
        }
    }

#pragma unroll
    for (int h = 0; h < 16; h++) {
        float2 x = unpack2(g[h][0]), y = unpack2(g[h][1]);
        *(float4*)(g_scratch + ((size_t)tile * HH + h) * HIDD + tid * 4) =
            make_float4(x.x, x.y, y.x, y.y);
    }
    {
        float2 x = unpack2(hb0), y = unpack2(hb1);
        *(float4*)(hbar_scratch + (size_t)tile * HIDD + tid * 4) =
            make_float4(x.x, x.y, y.x, y.y);
    }
}

// ============================================================
// K2: per (b,h): reduce g partials AND hbar partials, then
// kv/mv = (gsum|hsum) . Wv rows. grid 128, block 1024.
// (R7's merged kernel, measured 12.8us — replaces k2r+k2d+gap)
// ============================================================
__global__ void __launch_bounds__(1024)
k2_kvmv(const float* __restrict__ Wv) {
    int b = blockIdx.x >> 4, h = blockIdx.x & 15;
    __shared__ float gsum[HIDD];
    __shared__ float hsum[HIDD];

    int e = threadIdx.x;
    {
        float ag[4], ah[4];
#pragma unroll
        for (int j = 0; j < 4; j++) { ag[j] = 0.f; ah[j] = 0.f; }
        const float* gb = g_scratch + (((size_t)b * TILES) * HH + h) * HIDD + e;
        const float* hb = hbar_scratch + ((size_t)b * TILES) * HIDD + e;
#pragma unroll
        for (int c = 0; c < TILES; c += 4) {
            float tg[4], th[4];
#pragma unroll
            for (int j = 0; j < 4; j++) tg[j] = gb[(size_t)(c + j) * HH * HIDD];
#pragma unroll
            for (int j = 0; j < 4; j++) th[j] = hb[(size_t)(c + j) * HIDD];
#pragma unroll
            for (int j = 0; j < 4; j++) { ag[j] += tg[j]; ah[j] += th[j]; }
        }
        gsum[e] = (ag[0] + ag[1]) + (ag[2] + ag[3]);
        hsum[e] = (ah[0] + ah[1]) + (ah[2] + ah[3]);
    }
    __syncthreads();

    int w = threadIdx.x >> 5, l = threadIdx.x & 31;
#pragma unroll
    for (int dd = 0; dd < 2; dd++) {
        int d = w * 2 + dd;
        const float* wvrow = Wv + (size_t)(h * DHH + d) * HIDD;
        float ak = 0.f, am = 0.f;
#pragma unroll 8
        for (int e2 = l; e2 < HIDD; e2 += 32) {
            float wv = __ldg(wvrow + e2);
            ak += gsum[e2] * wv;
            am += hsum[e2] * wv;
        }
#pragma unroll
        for (int off = 16; off > 0; off >>= 1) {
            ak += __shfl_xor_sync(0xffffffffu, ak, off);
            am += __shfl_xor_sync(0xffffffffu, am, off);
        }
        if (l == 0) {
            kv_buf[((b * HH + h) << 6) + d] = ak;
            mv_buf[((b * HH + h) << 6) + d] = am;
        }
    }
}

// ============================================================
// K3: out = (qs*mv + kv)*invlen (R9)
// ============================================================
__global__ void k3_out(float* __restrict__ out) {
    int row0 = blockIdx.x << 3;
    int b = row0 >> 12;
    int t = threadIdx.x;
    int h = t >> 4;
    int d = (t & 15) << 2;
    float4 mv4 = *(const float4*)(mv_buf + ((b * HH + h) << 6) + d);
    float4 kv4 = *(const float4*)(kv_buf + ((b * HH + h) << 6) + d);
    float il = invlen_buf[b];
    float4 mvi = make_float4(mv4.x * il, mv4.y * il, mv4.z * il, mv4.w * il);
    float4 kvi = make_float4(kv4.x * il, kv4.y * il, kv4.z * il, kv4.w * il);
#pragma unroll
    for (int rr = 0; rr < 8; rr++) {
        int row = row0 + rr;
        float qsv = __ldg(qs_buf + (size_t)row * HH + h);
        float4 o;
        o.x = qsv * mvi.x + kvi.x;
        o.y = qsv * mvi.y + kvi.y;
        o.z = qsv * mvi.z + kvi.z;
        o.w = qsv * mvi.w + kvi.w;
        __stcs(((float4*)out) + (size_t)row * 256 + t, o);
    }
}

// ============================================================
extern "C" void kernel_launch(void* const* d_in, const int* in_sizes, int n_in,
                              void* d_out, int out_size) {
    const float* hidden = (const float*)d_in[0];
    const float* mask   = (const float*)d_in[1];
    const float* Wq     = (const float*)d_in[2];
    const float* Wk     = (const float*)d_in[3];
    const float* Wv     = (const float*)d_in[4];
    const float* aw     = (const float*)d_in[5];
    float* out = (float*)d_out;

    k0_weff<<<40, 256>>>(Wq, Wk, aw, mask);
    k1a_gemm<<<NBLK, 128>>>(hidden, mask);
    k1b_accum<<<NBLK, 256>>>(hidden, mask);
    k2_kvmv<<<BB * HH, 1024>>>(Wv);
    k3_out<<<BB * SS / 8, 256>>>(out);
}